// round 4
// baseline (speedup 1.0000x reference)
#include <cuda_runtime.h>
#include <cstdint>

// ============================================================================
// LinearDeepSeekV3: y = act_quant(x) @ dequant(weight)^T
// M=16384, N=256, K=7168, fp8 e4m3 weight with [128x128] block scales.
//
// Baseline-ISA design (harness PTX target is plain sm_103 — no 'a' features,
// so NO tcgen05/TMEM): legacy mma.sync.m16n8k32.e4m3 with fp32 accum.
// Exact reference numerics: raw fp8 operands per 128-k block, fold
// act_scale*weight_scale into fp32 register accumulator after each block.
//
// NEW in R3: the harness upcasts jnp.float8 inputs to float32 (prev round's
// rel_err≈600 == reading f32 bytes as e4m3). Canonicalize the weight into a
// __device__ fp8 buffer with device-side dtype auto-detection (graph-safe).
//
// CTA tile: M=64, N=256 (full), K streamed in 128-chunks, 2-stage cp.async
// pipeline. 8 warps; fused act-quant per chunk.
// ============================================================================

#define KDIM 7168
#define NDIM 256
#define KC 128
#define KB 56            // 7168/128
#define MT 64
#define NTH 256

// ---- shared memory layout (bytes) ----
#define OFF_XS 0                       // [2][64][128] f32   = 65536
#define OFF_BS 65536                   // [2][256][128] u8   = 65536 (swizzled)
#define OFF_AS 131072                  // [2][64][128] u8    = 16384 (swizzled)
#define OFF_SC 147456                  // [2][64] f32        = 512
#define OFF_WS 147968                  // [112] f32          = 448
#define SMEM_TOTAL 148416

__device__ __align__(16) uint8_t g_w8[(size_t)NDIM * KDIM];
__device__ int g_is_f32;

__device__ __forceinline__ uint32_t smem_u32(const void* p) {
    uint32_t a;
    asm("{ .reg .u64 t; cvta.to.shared.u64 t, %1; cvt.u32.u64 %0, t; }" : "=r"(a) : "l"(p));
    return a;
}

#define CP_ASYNC16(dst, src) \
    asm volatile("cp.async.cg.shared.global [%0], [%1], 16;" :: "r"(dst), "l"(src) : "memory")

#define LDMATRIX_X4(r0, r1, r2, r3, addr) \
    asm volatile("ldmatrix.sync.aligned.m8n8.x4.shared.b16 {%0,%1,%2,%3}, [%4];" \
        : "=r"(r0), "=r"(r1), "=r"(r2), "=r"(r3) : "r"(addr))

#define MMA_E4M3(d0, d1, d2, d3, a0, a1, a2, a3, b0, b1) \
    asm volatile("mma.sync.aligned.m16n8k32.row.col.f32.e4m3.e4m3.f32 " \
        "{%0,%1,%2,%3}, {%4,%5,%6,%7}, {%8,%9}, {%0,%1,%2,%3};" \
        : "+f"(d0), "+f"(d1), "+f"(d2), "+f"(d3) \
        : "r"(a0), "r"(a1), "r"(a2), "r"(a3), "r"(b0), "r"(b1))

// ============================================================================
// Weight canonicalization: detect f32-vs-raw-fp8, emit e4m3 bytes to g_w8
// ============================================================================
__global__ void detect_kernel(const float* wf) {
    __shared__ int cnt;
    if (threadIdx.x == 0) cnt = 0;
    __syncthreads();
    int ok = 0;
    for (int i = threadIdx.x; i < 4096; i += blockDim.x) {
        float v = wf[i];
        if (isfinite(v) && fabsf(v) <= 1.0f) ok++;
    }
    atomicAdd(&cnt, ok);
    __syncthreads();
    if (threadIdx.x == 0) g_is_f32 = (cnt >= 4000) ? 1 : 0;
}

__global__ void conv_kernel(const void* w) {
    const int i4 = blockIdx.x * blockDim.x + threadIdx.x;   // 4 elems per thread
    constexpr int TOT4 = NDIM * KDIM / 4;
    if (i4 >= TOT4) return;
    uint32_t outw;
    if (g_is_f32) {
        const float4 v = ((const float4*)w)[i4];
        unsigned short lo, hi;
        asm("cvt.rn.satfinite.e4m3x2.f32 %0, %1, %2;" : "=h"(lo) : "f"(v.y), "f"(v.x));
        asm("cvt.rn.satfinite.e4m3x2.f32 %0, %1, %2;" : "=h"(hi) : "f"(v.w), "f"(v.z));
        outw = (uint32_t)lo | ((uint32_t)hi << 16);
    } else {
        outw = ((const uint32_t*)w)[i4];
    }
    ((uint32_t*)g_w8)[i4] = outw;
}

// ============================================================================
// Fused act-quant + fp8 mma GEMM
// ============================================================================
struct IssueCtx {
    const float* x;
    size_t m0cta;
    uint32_t sb;
    int tid;
};

__device__ __forceinline__ void issue_chunk(const IssueCtx& c, int kc, int st) {
    // ---- x tile: 64 rows x 128 f32 (512B/row), coalesced 16B chunks ----
    {
        const int col = c.tid & 31;
        const int rb = c.tid >> 5;
        const size_t gbase = c.m0cta * KDIM + (size_t)kc * KC;
#pragma unroll
        for (int i = 0; i < 8; ++i) {
            const int row = rb + i * 8;
            const uint32_t dst = c.sb + OFF_XS + st * 32768 + row * 512 + col * 16;
            const float* g = c.x + gbase + (size_t)row * KDIM + col * 4;
            CP_ASYNC16(dst, g);
        }
    }
    // ---- B tile: 256 rows(n) x 128 fp8 from g_w8, swizzled 16B units ----
    {
        const int b16 = c.tid & 7;
        const int nb_ = c.tid >> 3;
#pragma unroll
        for (int i = 0; i < 8; ++i) {
            const int n = nb_ + i * 32;
            const uint32_t dst = c.sb + OFF_BS + st * 32768 + n * 128 + ((b16 ^ (n & 7)) * 16);
            const uint8_t* g = g_w8 + (size_t)n * KDIM + (size_t)kc * KC + b16 * 16;
            CP_ASYNC16(dst, g);
        }
    }
    asm volatile("cp.async.commit_group;" ::: "memory");
}

__global__ void __launch_bounds__(NTH, 1)
fused_fp8_gemm(const float* __restrict__ x, const float* __restrict__ ws,
               float* __restrict__ out) {
    extern __shared__ char smem[];
    const uint32_t sb = smem_u32(smem);
    const int tid = threadIdx.x;
    const int lane = tid & 31;
    const int wid = tid >> 5;
    const size_t m0cta = (size_t)blockIdx.x * MT;

    if (tid < 112) *(float*)(smem + OFF_WS + tid * 4) = ws[tid];

    IssueCtx ic{x, m0cta, sb, tid};
    issue_chunk(ic, 0, 0);
    issue_chunk(ic, 1, 1);

    float acc[64];
#pragma unroll
    for (int i = 0; i < 64; ++i) acc[i] = 0.f;

    const int h = wid >> 2;                  // n-half (0: n<128, 1: n>=128)
    const int m0 = (wid & 3) * 16;           // warp's m rows within tile
    const int arow = m0 + (lane & 15);
    const int asel0 = lane >> 4;
    const int nlane = (lane & 7) + ((lane >> 4) << 3);
    const int bsel0 = (lane >> 3) & 1;

    for (int kc = 0; kc < KB; ++kc) {
        const int st = kc & 1;
        if (kc < KB - 2) { asm volatile("cp.async.wait_group 1;" ::: "memory"); }
        else             { asm volatile("cp.async.wait_group 0;" ::: "memory"); }
        __syncthreads();

        // ================= act-quant: 8 rows per warp =================
        {
            const uint32_t xb = sb + OFF_XS + st * 32768;
            const uint32_t ab = sb + OFF_AS + st * 8192;
            float4 v[8];
#pragma unroll
            for (int r = 0; r < 8; ++r) {
                const uint32_t a_ = xb + (wid * 8 + r) * 512 + lane * 16;
                asm volatile("ld.shared.v4.f32 {%0,%1,%2,%3}, [%4];"
                    : "=f"(v[r].x), "=f"(v[r].y), "=f"(v[r].z), "=f"(v[r].w) : "r"(a_));
            }
            float am[8];
#pragma unroll
            for (int r = 0; r < 8; ++r)
                am[r] = fmaxf(fmaxf(fabsf(v[r].x), fabsf(v[r].y)),
                              fmaxf(fabsf(v[r].z), fabsf(v[r].w)));
#pragma unroll
            for (int o = 16; o; o >>= 1) {
#pragma unroll
                for (int r = 0; r < 8; ++r)
                    am[r] = fmaxf(am[r], __shfl_xor_sync(0xffffffffu, am[r], o));
            }
#pragma unroll
            for (int r = 0; r < 8; ++r) {
                const int row = wid * 8 + r;
                const float amax = fmaxf(am[r], 1e-8f);
                const float s = __fdiv_rn(amax, 448.0f);    // matches jnp RN divide
                const float ri = __fdiv_rn(448.0f, amax);
                unsigned short lo16, hi16;
                asm("cvt.rn.satfinite.e4m3x2.f32 %0, %1, %2;"
                    : "=h"(lo16) : "f"(v[r].y * ri), "f"(v[r].x * ri));
                asm("cvt.rn.satfinite.e4m3x2.f32 %0, %1, %2;"
                    : "=h"(hi16) : "f"(v[r].w * ri), "f"(v[r].z * ri));
                const uint32_t word = (uint32_t)lo16 | ((uint32_t)hi16 << 16);
                const uint32_t a_ = ab + row * 128 + (((lane >> 2) ^ (row & 7)) * 16) + (lane & 3) * 4;
                asm volatile("st.shared.b32 [%0], %1;" :: "r"(a_), "r"(word) : "memory");
                if (lane == 0) *(float*)(smem + OFF_SC + st * 256 + row * 4) = s;
            }
        }
        __syncthreads();

        // ================= mma: m16 x n128 per warp, k128 =================
        {
            const uint32_t ab = sb + OFF_AS + st * 8192;
            const uint32_t bb = sb + OFF_BS + st * 32768;
            uint32_t a[4][4];
#pragma unroll
            for (int ks = 0; ks < 4; ++ks) {
                const uint32_t ad = ab + arow * 128 + (((ks * 2 + asel0) ^ (arow & 7)) * 16);
                LDMATRIX_X4(a[ks][0], a[ks][1], a[ks][2], a[ks][3], ad);
            }
            const float s0 = *(float*)(smem + OFF_SC + st * 256 + (m0 + (lane >> 2)) * 4);
            const float s1 = *(float*)(smem + OFF_SC + st * 256 + (m0 + (lane >> 2) + 8) * 4);
            const float wv = *(float*)(smem + OFF_WS + (h * 56 + kc) * 4);
            const float f0 = s0 * wv;
            const float f1 = s1 * wv;
#pragma unroll
            for (int half = 0; half < 2; ++half) {
                float p[32];
#pragma unroll
                for (int i = 0; i < 32; ++i) p[i] = 0.f;
#pragma unroll
                for (int ks = 0; ks < 4; ++ks) {
#pragma unroll
                    for (int g = 0; g < 4; ++g) {
                        const int nb = h * 128 + half * 64 + g * 16 + nlane;
                        const uint32_t bd = bb + nb * 128 + (((ks * 2 + bsel0) ^ (nb & 7)) * 16);
                        uint32_t b0, b1, b2, b3;
                        LDMATRIX_X4(b0, b1, b2, b3, bd);
                        MMA_E4M3(p[g*8+0], p[g*8+1], p[g*8+2], p[g*8+3],
                                 a[ks][0], a[ks][1], a[ks][2], a[ks][3], b0, b1);
                        MMA_E4M3(p[g*8+4], p[g*8+5], p[g*8+6], p[g*8+7],
                                 a[ks][0], a[ks][1], a[ks][2], a[ks][3], b2, b3);
                    }
                }
#pragma unroll
                for (int t = 0; t < 8; ++t) {
                    acc[half*32+t*4+0] = fmaf(p[t*4+0], f0, acc[half*32+t*4+0]);
                    acc[half*32+t*4+1] = fmaf(p[t*4+1], f0, acc[half*32+t*4+1]);
                    acc[half*32+t*4+2] = fmaf(p[t*4+2], f1, acc[half*32+t*4+2]);
                    acc[half*32+t*4+3] = fmaf(p[t*4+3], f1, acc[half*32+t*4+3]);
                }
            }
        }
        __syncthreads();
        if (kc + 2 < KB) issue_chunk(ic, kc + 2, st);
    }

    // ================= epilogue =================
    {
        const size_t mr = m0cta + m0 + (lane >> 2);
        float* o0 = out + mr * NDIM;
#pragma unroll
        for (int half = 0; half < 2; ++half) {
#pragma unroll
            for (int t = 0; t < 8; ++t) {
                const int n = h * 128 + half * 64 + t * 8 + (lane & 3) * 2;
                float2 u = make_float2(acc[half*32+t*4+0], acc[half*32+t*4+1]);
                float2 d = make_float2(acc[half*32+t*4+2], acc[half*32+t*4+3]);
                *(float2*)(o0 + n) = u;
                *(float2*)(o0 + 8 * NDIM + n) = d;
            }
        }
    }
}

// ============================================================================
extern "C" void kernel_launch(void* const* d_in, const int* in_sizes, int n_in,
                              void* d_out, int out_size) {
    const float* x = (const float*)d_in[0];
    const void* w = d_in[1];
    const float* ws = (const float*)d_in[2];
    float* out = (float*)d_out;

    const int M = in_sizes[0] / KDIM;       // 16384
    const int grid = M / MT;                // 256

    cudaFuncSetAttribute(fused_fp8_gemm, cudaFuncAttributeMaxDynamicSharedMemorySize, SMEM_TOTAL);

    detect_kernel<<<1, 256>>>((const float*)w);
    conv_kernel<<<(NDIM * KDIM / 4 + 255) / 256, 256>>>(w);
    fused_fp8_gemm<<<grid, NTH, SMEM_TOTAL>>>(x, ws, out);
}

// round 5
// speedup vs baseline: 1.0685x; 1.0685x over previous
#include <cuda_runtime.h>
#include <cstdint>

// ============================================================================
// LinearDeepSeekV3: y = act_quant(x) @ dequant(weight)^T
// M=16384, N=256, K=7168, fp8 e4m3 weight with [128x128] block scales.
// Baseline-ISA (plain sm_103): legacy mma.sync.m16n8k32.e4m3, fp32 accum,
// per-k-block scale fold (exact reference reassociation).
//
// R4: MT=128 (grid 128 = 1 wave), 8 warps, warp tile m64xn64 (4x less B
// ldmatrix redundancy), single-buffered X/A/scales, 2-stage B, X refill
// overlapped with MMA. Weight canonicalized to fp8 by conv kernel with
// per-block inline dtype detection (harness upcasts fp8 inputs to f32).
// ============================================================================

#define KDIM 7168
#define NDIM 256
#define KC 128
#define KB 56
#define MT 128
#define NTH 256

// ---- shared memory layout (bytes) ----
#define OFF_XS 0            // [128][128] f32 = 65536  (single stage, swizzled)
#define OFF_BS 65536        // [2][256][128] u8 = 65536 (swizzled)
#define OFF_AS 131072       // [128][128] u8 = 16384   (single stage, swizzled)
#define OFF_SC 147456       // [128] f32 = 512         (single stage)
#define OFF_WS 147968       // [112] f32
#define SMEM_TOTAL 148416

__device__ __align__(16) uint8_t g_w8[(size_t)NDIM * KDIM];

__device__ __forceinline__ uint32_t smem_u32(const void* p) {
    uint32_t a;
    asm("{ .reg .u64 t; cvta.to.shared.u64 t, %1; cvt.u32.u64 %0, t; }" : "=r"(a) : "l"(p));
    return a;
}

#define CP_ASYNC16(dst, src) \
    asm volatile("cp.async.cg.shared.global [%0], [%1], 16;" :: "r"(dst), "l"(src) : "memory")

#define LDMATRIX_X4(r0, r1, r2, r3, addr) \
    asm volatile("ldmatrix.sync.aligned.m8n8.x4.shared.b16 {%0,%1,%2,%3}, [%4];" \
        : "=r"(r0), "=r"(r1), "=r"(r2), "=r"(r3) : "r"(addr))

#define MMA_E4M3(d0, d1, d2, d3, a0, a1, a2, a3, b0, b1) \
    asm volatile("mma.sync.aligned.m16n8k32.row.col.f32.e4m3.e4m3.f32 " \
        "{%0,%1,%2,%3}, {%4,%5,%6,%7}, {%8,%9}, {%0,%1,%2,%3};" \
        : "+f"(d0), "+f"(d1), "+f"(d2), "+f"(d3) \
        : "r"(a0), "r"(a1), "r"(a2), "r"(a3), "r"(b0), "r"(b1))

// ============================================================================
// Weight canonicalization (inline per-block dtype detection; deterministic:
// every block tests the SAME first 4096 elements)
// ============================================================================
__global__ void conv_kernel(const void* w) {
    __shared__ int cnt;
    const int tid = threadIdx.x;
    if (tid == 0) cnt = 0;
    __syncthreads();
    const float* wf = (const float*)w;
    int ok = 0;
#pragma unroll
    for (int i = 0; i < 16; ++i) {
        float v = wf[tid + i * 256];
        if (isfinite(v) && fabsf(v) <= 1.0f) ok++;
    }
#pragma unroll
    for (int o = 16; o; o >>= 1) ok += __shfl_xor_sync(0xffffffffu, ok, o);
    if ((tid & 31) == 0) atomicAdd(&cnt, ok);
    __syncthreads();
    const bool is_f32 = (cnt >= 4000);

    const int i4 = blockIdx.x * 256 + tid;    // 4 elems per thread
    constexpr int TOT4 = NDIM * KDIM / 4;
    if (i4 >= TOT4) return;
    uint32_t outw;
    if (is_f32) {
        const float4 v = ((const float4*)w)[i4];
        unsigned short lo, hi;
        asm("cvt.rn.satfinite.e4m3x2.f32 %0, %1, %2;" : "=h"(lo) : "f"(v.y), "f"(v.x));
        asm("cvt.rn.satfinite.e4m3x2.f32 %0, %1, %2;" : "=h"(hi) : "f"(v.w), "f"(v.z));
        outw = (uint32_t)lo | ((uint32_t)hi << 16);
    } else {
        outw = ((const uint32_t*)w)[i4];
    }
    ((uint32_t*)g_w8)[i4] = outw;
}

// ============================================================================
// Fused act-quant + fp8 mma GEMM
// ============================================================================
__device__ __forceinline__ void issue_x(const float* x, size_t m0cta, uint32_t sb,
                                        int tid, int kc) {
    const int col = tid & 31;            // 16B unit within 512B row
    const int rb = tid >> 5;             // 0..7
#pragma unroll
    for (int i = 0; i < 16; ++i) {
        const int row = rb + i * 8;
        const uint32_t dst = sb + OFF_XS + row * 512 + ((col ^ (row & 31)) * 16);
        const float* g = x + (m0cta + row) * KDIM + (size_t)kc * KC + col * 4;
        CP_ASYNC16(dst, g);
    }
}

__device__ __forceinline__ void issue_b(uint32_t sb, int tid, int kc, int st) {
    const int b16 = tid & 7;
    const int nb_ = tid >> 3;            // 0..31
#pragma unroll
    for (int i = 0; i < 8; ++i) {
        const int n = nb_ + i * 32;
        const uint32_t dst = sb + OFF_BS + st * 32768 + n * 128 + ((b16 ^ (n & 7)) * 16);
        const uint8_t* g = g_w8 + (size_t)n * KDIM + (size_t)kc * KC + b16 * 16;
        CP_ASYNC16(dst, g);
    }
}

__global__ void __launch_bounds__(NTH, 1)
fused_fp8_gemm(const float* __restrict__ x, const float* __restrict__ ws,
               float* __restrict__ out) {
    extern __shared__ char smem[];
    const uint32_t sb = smem_u32(smem);
    const int tid = threadIdx.x;
    const int lane = tid & 31;
    const int wid = tid >> 5;
    const size_t m0cta = (size_t)blockIdx.x * MT;

    if (tid < 112) ((float*)(smem + OFF_WS))[tid] = ws[tid];

    // quant role: 2 threads per row, 64 cols each
    const int qrow = tid >> 1;
    const int qq = tid & 1;
    // mma role: warp grid 2m x 4n, warp tile m64 x n64
    const int wm = wid >> 2, wn = wid & 3;
    const int R0 = wm * 64, C0 = wn * 64;
    const int nb = wn >> 1;
    const int alane = lane & 15, asel = lane >> 4;
    const int nlane = (lane & 7) | ((lane >> 4) << 3);
    const int bsel = (lane >> 3) & 1;
    const int lr = lane >> 2;

    float acc[128];
#pragma unroll
    for (int i = 0; i < 128; ++i) acc[i] = 0.f;

    issue_x(x, m0cta, sb, tid, 0);
    issue_b(sb, tid, 0, 0);
    asm volatile("cp.async.commit_group;" ::: "memory");
    issue_b(sb, tid, 1, 1);
    asm volatile("cp.async.commit_group;" ::: "memory");

    const float* SC = (const float*)(smem + OFF_SC);

#pragma unroll 1
    for (int kc = 0; kc < KB; ++kc) {
        const int st = kc & 1;
        if (kc == KB - 1) { asm volatile("cp.async.wait_group 0;" ::: "memory"); }
        else              { asm volatile("cp.async.wait_group 1;" ::: "memory"); }
        __syncthreads();

        // ================= act-quant (exact reference numerics) =================
        {
            float4 v[16];
#pragma unroll
            for (int i = 0; i < 16; ++i) {
                const uint32_t u = (uint32_t)((qq * 16 + i) ^ (qrow & 31));
                const uint32_t a_ = sb + OFF_XS + qrow * 512 + u * 16;
                asm volatile("ld.shared.v4.f32 {%0,%1,%2,%3}, [%4];"
                    : "=f"(v[i].x), "=f"(v[i].y), "=f"(v[i].z), "=f"(v[i].w) : "r"(a_));
            }
            float am = 0.f;
#pragma unroll
            for (int i = 0; i < 16; ++i)
                am = fmaxf(am, fmaxf(fmaxf(fabsf(v[i].x), fabsf(v[i].y)),
                                     fmaxf(fabsf(v[i].z), fabsf(v[i].w))));
            am = fmaxf(am, __shfl_xor_sync(0xffffffffu, am, 1));
            const float amax = fmaxf(am, 1e-8f);
            const float s = __fdiv_rn(amax, 448.0f);
            const float ri = __fdiv_rn(448.0f, amax);
            uint32_t w[16];
#pragma unroll
            for (int i = 0; i < 16; ++i) {
                unsigned short lo, hi;
                asm("cvt.rn.satfinite.e4m3x2.f32 %0, %1, %2;"
                    : "=h"(lo) : "f"(v[i].y * ri), "f"(v[i].x * ri));
                asm("cvt.rn.satfinite.e4m3x2.f32 %0, %1, %2;"
                    : "=h"(hi) : "f"(v[i].w * ri), "f"(v[i].z * ri));
                w[i] = (uint32_t)lo | ((uint32_t)hi << 16);
            }
#pragma unroll
            for (int j = 0; j < 4; ++j) {
                const uint32_t unit = (uint32_t)((qq * 4 + j) ^ (qrow & 7));
                const uint32_t a_ = sb + OFF_AS + qrow * 128 + unit * 16;
                asm volatile("st.shared.v4.b32 [%0], {%1,%2,%3,%4};"
                    :: "r"(a_), "r"(w[4*j]), "r"(w[4*j+1]), "r"(w[4*j+2]), "r"(w[4*j+3])
                    : "memory");
            }
            if (qq == 0) ((float*)(smem + OFF_SC))[qrow] = s;
        }
        __syncthreads();

        // refill single X buffer for next chunk; overlaps with MMA below
        if (kc + 1 < KB) {
            issue_x(x, m0cta, sb, tid, kc + 1);
            asm volatile("cp.async.commit_group;" ::: "memory");
        }

        // ================= mma: warp tile m64 x n64, k128 =================
        {
            const uint32_t ab = sb + OFF_AS;
            const uint32_t bb = sb + OFF_BS + st * 32768;
            const float wv = ((const float*)(smem + OFF_WS))[nb * 56 + kc];
#pragma unroll
            for (int mh = 0; mh < 2; ++mh) {
                const int rbase = R0 + mh * 32;
                float p[64];
#pragma unroll
                for (int i = 0; i < 64; ++i) p[i] = 0.f;
#pragma unroll
                for (int ks = 0; ks < 4; ++ks) {
                    uint32_t a0[4], a1[4];
                    {
                        int r = rbase + alane;
                        uint32_t ad = ab + r * 128 + (((ks * 2 + asel) ^ (r & 7)) * 16);
                        LDMATRIX_X4(a0[0], a0[1], a0[2], a0[3], ad);
                        r = rbase + 16 + alane;
                        ad = ab + r * 128 + (((ks * 2 + asel) ^ (r & 7)) * 16);
                        LDMATRIX_X4(a1[0], a1[1], a1[2], a1[3], ad);
                    }
#pragma unroll
                    for (int g = 0; g < 4; ++g) {
                        const int nr = C0 + g * 16 + nlane;
                        const uint32_t bd = bb + nr * 128 + (((ks * 2 + bsel) ^ (nr & 7)) * 16);
                        uint32_t b0, b1, b2, b3;
                        LDMATRIX_X4(b0, b1, b2, b3, bd);
                        MMA_E4M3(p[g*8+0], p[g*8+1], p[g*8+2], p[g*8+3],
                                 a0[0], a0[1], a0[2], a0[3], b0, b1);
                        MMA_E4M3(p[g*8+4], p[g*8+5], p[g*8+6], p[g*8+7],
                                 a0[0], a0[1], a0[2], a0[3], b2, b3);
                        MMA_E4M3(p[32+g*8+0], p[32+g*8+1], p[32+g*8+2], p[32+g*8+3],
                                 a1[0], a1[1], a1[2], a1[3], b0, b1);
                        MMA_E4M3(p[32+g*8+4], p[32+g*8+5], p[32+g*8+6], p[32+g*8+7],
                                 a1[0], a1[1], a1[2], a1[3], b2, b3);
                    }
                }
                // fold per-block scales into fp32 accumulator
                const float f00 = SC[rbase + lr] * wv;
                const float f01 = SC[rbase + lr + 8] * wv;
                const float f10 = SC[rbase + 16 + lr] * wv;
                const float f11 = SC[rbase + 24 + lr] * wv;
#pragma unroll
                for (int g = 0; g < 4; ++g) {
#pragma unroll
                    for (int h8 = 0; h8 < 2; ++h8) {
                        const int pi = g * 8 + h8 * 4;
                        const int ai = mh * 64 + pi;
                        acc[ai+0] = fmaf(p[pi+0], f00, acc[ai+0]);
                        acc[ai+1] = fmaf(p[pi+1], f00, acc[ai+1]);
                        acc[ai+2] = fmaf(p[pi+2], f01, acc[ai+2]);
                        acc[ai+3] = fmaf(p[pi+3], f01, acc[ai+3]);
                        const int pj = 32 + pi;
                        const int aj = mh * 64 + pj;
                        acc[aj+0] = fmaf(p[pj+0], f10, acc[aj+0]);
                        acc[aj+1] = fmaf(p[pj+1], f10, acc[aj+1]);
                        acc[aj+2] = fmaf(p[pj+2], f11, acc[aj+2]);
                        acc[aj+3] = fmaf(p[pj+3], f11, acc[aj+3]);
                    }
                }
            }
        }
        __syncthreads();
        if (kc + 2 < KB) {
            issue_b(sb, tid, kc + 2, st);
            asm volatile("cp.async.commit_group;" ::: "memory");
        }
    }

    // ================= epilogue =================
#pragma unroll
    for (int mh = 0; mh < 2; ++mh) {
#pragma unroll
        for (int s = 0; s < 2; ++s) {
            const int row = R0 + mh * 32 + s * 16 + lr;
            float* o0 = out + (m0cta + row) * NDIM;
#pragma unroll
            for (int g = 0; g < 4; ++g) {
#pragma unroll
                for (int h8 = 0; h8 < 2; ++h8) {
                    const int base = mh * 64 + s * 32 + g * 8 + h8 * 4;
                    const int col = C0 + g * 16 + h8 * 8 + (lane & 3) * 2;
                    *(float2*)(o0 + col) = make_float2(acc[base], acc[base+1]);
                    *(float2*)(o0 + 8 * NDIM + col) = make_float2(acc[base+2], acc[base+3]);
                }
            }
        }
    }
}

// ============================================================================
extern "C" void kernel_launch(void* const* d_in, const int* in_sizes, int n_in,
                              void* d_out, int out_size) {
    const float* x = (const float*)d_in[0];
    const void* w = d_in[1];
    const float* ws = (const float*)d_in[2];
    float* out = (float*)d_out;

    const int M = in_sizes[0] / KDIM;       // 16384
    const int grid = M / MT;                // 128

    cudaFuncSetAttribute(fused_fp8_gemm, cudaFuncAttributeMaxDynamicSharedMemorySize, SMEM_TOTAL);

    conv_kernel<<<(NDIM * KDIM / 4 + 255) / 256, 256>>>(w);
    fused_fp8_gemm<<<grid, NTH, SMEM_TOTAL>>>(x, ws, out);
}

// round 6
// speedup vs baseline: 1.1353x; 1.0625x over previous
#include <cuda_runtime.h>
#include <cstdint>

// ============================================================================
// LinearDeepSeekV3: y = act_quant(x) @ dequant(weight)^T
// M=16384, N=256, K=7168, fp8 e4m3 weight with [128x128] block scales.
// Baseline-ISA (plain sm_103): legacy mma.sync.m16n8k32.e4m3, fp32 accum,
// per-k-block scale fold (exact reference reassociation).
//
// R5: occupancy attack. MT=64, grid=256, __launch_bounds__(256,2) -> 2 CTAs
// per SM so one CTA's quant/barrier time overlaps the other's MMA. Warp tile
// m32xn64 with n32-split partials to fit the 128-reg cap. Conflict-free
// swizzles for X reads and A stores. X single-stage (refill overlaps MMA),
// B double-buffered.
// ============================================================================

#define KDIM 7168
#define NDIM 256
#define KC 128
#define KB 56
#define MT 64
#define NTH 256

// ---- shared memory layout (bytes) ----
#define OFF_XS 0            // [64][128] f32 = 32768 (swizzled, single stage)
#define OFF_BS 32768        // [2][256][128] u8 = 65536 (swizzled)
#define OFF_AS 98304        // [64][128] u8 = 8192 (swizzled, single stage)
#define OFF_SC 106496       // [64] f32 = 256
#define OFF_WS 106752       // [112] f32 = 448
#define SMEM_TOTAL 107200

__device__ __align__(16) uint8_t g_w8[(size_t)NDIM * KDIM];

__device__ __forceinline__ uint32_t smem_u32(const void* p) {
    uint32_t a;
    asm("{ .reg .u64 t; cvta.to.shared.u64 t, %1; cvt.u32.u64 %0, t; }" : "=r"(a) : "l"(p));
    return a;
}

#define CP_ASYNC16(dst, src) \
    asm volatile("cp.async.cg.shared.global [%0], [%1], 16;" :: "r"(dst), "l"(src) : "memory")

#define LDMATRIX_X4(r0, r1, r2, r3, addr) \
    asm volatile("ldmatrix.sync.aligned.m8n8.x4.shared.b16 {%0,%1,%2,%3}, [%4];" \
        : "=r"(r0), "=r"(r1), "=r"(r2), "=r"(r3) : "r"(addr))

#define MMA_E4M3(d0, d1, d2, d3, a0, a1, a2, a3, b0, b1) \
    asm volatile("mma.sync.aligned.m16n8k32.row.col.f32.e4m3.e4m3.f32 " \
        "{%0,%1,%2,%3}, {%4,%5,%6,%7}, {%8,%9}, {%0,%1,%2,%3};" \
        : "+f"(d0), "+f"(d1), "+f"(d2), "+f"(d3) \
        : "r"(a0), "r"(a1), "r"(a2), "r"(a3), "r"(b0), "r"(b1))

// ============================================================================
// Weight canonicalization (harness upcasts fp8 inputs to f32; detect + cvt).
// Deterministic: every block tests the SAME first 4096 elements.
// ============================================================================
__global__ void conv_kernel(const void* w) {
    __shared__ int cnt;
    const int tid = threadIdx.x;
    if (tid == 0) cnt = 0;
    __syncthreads();
    const float* wf = (const float*)w;
    int ok = 0;
#pragma unroll
    for (int i = 0; i < 16; ++i) {
        float v = wf[tid + i * 256];
        if (isfinite(v) && fabsf(v) <= 1.0f) ok++;
    }
#pragma unroll
    for (int o = 16; o; o >>= 1) ok += __shfl_xor_sync(0xffffffffu, ok, o);
    if ((tid & 31) == 0) atomicAdd(&cnt, ok);
    __syncthreads();
    const bool is_f32 = (cnt >= 4000);

    const int i4 = blockIdx.x * 256 + tid;
    constexpr int TOT4 = NDIM * KDIM / 4;
    if (i4 >= TOT4) return;
    uint32_t outw;
    if (is_f32) {
        const float4 v = ((const float4*)w)[i4];
        unsigned short lo, hi;
        asm("cvt.rn.satfinite.e4m3x2.f32 %0, %1, %2;" : "=h"(lo) : "f"(v.y), "f"(v.x));
        asm("cvt.rn.satfinite.e4m3x2.f32 %0, %1, %2;" : "=h"(hi) : "f"(v.w), "f"(v.z));
        outw = (uint32_t)lo | ((uint32_t)hi << 16);
    } else {
        outw = ((const uint32_t*)w)[i4];
    }
    ((uint32_t*)g_w8)[i4] = outw;
}

// ============================================================================
// Fused act-quant + fp8 mma GEMM
// ============================================================================
__device__ __forceinline__ void issue_x(const float* x, size_t m0cta, uint32_t sb,
                                        int tid, int kc) {
    const int col = tid & 31;                 // 16B unit (32 per 512B row)
    const int rb = tid >> 5;                  // 0..7
#pragma unroll
    for (int i = 0; i < 8; ++i) {
        const int row = rb + i * 8;
        const uint32_t dst = sb + OFF_XS + row * 512 + ((col ^ ((row & 7) * 4)) * 16);
        const float* g = x + (m0cta + row) * KDIM + (size_t)kc * KC + col * 4;
        CP_ASYNC16(dst, g);
    }
}

__device__ __forceinline__ void issue_b(uint32_t sb, int tid, int kc, int st) {
    const int b16 = tid & 7;
    const int nb_ = tid >> 3;                 // 0..31
#pragma unroll
    for (int i = 0; i < 8; ++i) {
        const int n = nb_ + i * 32;
        const uint32_t dst = sb + OFF_BS + st * 32768 + n * 128 + ((b16 ^ (n & 7)) * 16);
        const uint8_t* g = g_w8 + (size_t)n * KDIM + (size_t)kc * KC + b16 * 16;
        CP_ASYNC16(dst, g);
    }
}

__global__ void __launch_bounds__(NTH, 2)
fused_fp8_gemm(const float* __restrict__ x, const float* __restrict__ ws,
               float* __restrict__ out) {
    extern __shared__ char smem[];
    const uint32_t sb = smem_u32(smem);
    const int tid = threadIdx.x;
    const int lane = tid & 31;
    const int wid = tid >> 5;
    const size_t m0cta = (size_t)blockIdx.x * MT;

    if (tid < 112) ((float*)(smem + OFF_WS))[tid] = ws[tid];

    // quant role: 4 threads per row, 32 cols each
    const int qrow = tid >> 2;
    const int qq = tid & 3;
    const int qsw = (qrow & 7) * 4;
    // mma role: warp grid 2m x 4n, warp tile m32 x n64
    const int R0 = (wid >> 2) * 32;
    const int C0 = (wid & 3) * 64;
    const int nb = (wid & 3) >> 1;
    const int alane = lane & 15, asel = lane >> 4;
    const int nlane = (lane & 7) | ((lane >> 4) << 3);
    const int bsel = (lane >> 3) & 1;
    const int lr = lane >> 2;

    float acc[64];
#pragma unroll
    for (int i = 0; i < 64; ++i) acc[i] = 0.f;

    issue_x(x, m0cta, sb, tid, 0);
    issue_b(sb, tid, 0, 0);
    asm volatile("cp.async.commit_group;" ::: "memory");
    issue_b(sb, tid, 1, 1);
    asm volatile("cp.async.commit_group;" ::: "memory");

    const float* SC = (const float*)(smem + OFF_SC);

#pragma unroll 1
    for (int kc = 0; kc < KB; ++kc) {
        const int st = kc & 1;
        if (kc == KB - 1) { asm volatile("cp.async.wait_group 0;" ::: "memory"); }
        else              { asm volatile("cp.async.wait_group 1;" ::: "memory"); }
        __syncthreads();

        // ===== act-quant (exact reference numerics); low live-reg version =====
        {
            float4 v[8];
#pragma unroll
            for (int i = 0; i < 8; ++i) {
                const uint32_t phys = (uint32_t)((i * 4 + qq) ^ qsw);
                const uint32_t a_ = sb + OFF_XS + qrow * 512 + phys * 16;
                asm volatile("ld.shared.v4.f32 {%0,%1,%2,%3}, [%4];"
                    : "=f"(v[i].x), "=f"(v[i].y), "=f"(v[i].z), "=f"(v[i].w) : "r"(a_));
            }
            float am = 0.f;
#pragma unroll
            for (int i = 0; i < 8; ++i)
                am = fmaxf(am, fmaxf(fmaxf(fabsf(v[i].x), fabsf(v[i].y)),
                                     fmaxf(fabsf(v[i].z), fabsf(v[i].w))));
            am = fmaxf(am, __shfl_xor_sync(0xffffffffu, am, 1));
            am = fmaxf(am, __shfl_xor_sync(0xffffffffu, am, 2));
            const float amax = fmaxf(am, 1e-8f);
            const float s = __fdiv_rn(amax, 448.0f);
            const float ri = __fdiv_rn(448.0f, amax);
#pragma unroll
            for (int i = 0; i < 8; ++i) {
                unsigned short lo, hi;
                asm("cvt.rn.satfinite.e4m3x2.f32 %0, %1, %2;"
                    : "=h"(lo) : "f"(v[i].y * ri), "f"(v[i].x * ri));
                asm("cvt.rn.satfinite.e4m3x2.f32 %0, %1, %2;"
                    : "=h"(hi) : "f"(v[i].w * ri), "f"(v[i].z * ri));
                const uint32_t word = (uint32_t)lo | ((uint32_t)hi << 16);
                const uint32_t a_ = sb + OFF_AS + qrow * 128 + ((i ^ (qrow & 7)) * 16) + qq * 4;
                asm volatile("st.shared.b32 [%0], %1;" :: "r"(a_), "r"(word) : "memory");
            }
            if (qq == 0) ((float*)(smem + OFF_SC))[qrow] = s;
        }
        __syncthreads();

        // refill single X buffer for next chunk; overlaps with MMA below
        if (kc + 1 < KB) {
            issue_x(x, m0cta, sb, tid, kc + 1);
            asm volatile("cp.async.commit_group;" ::: "memory");
        }

        // ===== mma: warp tile m32 x n64 (two n32 passes), k128 =====
        {
            const uint32_t ab = sb + OFF_AS;
            const uint32_t bb = sb + OFF_BS + st * 32768;
            const float wv = ((const float*)(smem + OFF_WS))[nb * 56 + kc];
#pragma unroll
            for (int g2 = 0; g2 < 2; ++g2) {
                float p[32];
#pragma unroll
                for (int i = 0; i < 32; ++i) p[i] = 0.f;
#pragma unroll
                for (int ks = 0; ks < 4; ++ks) {
                    uint32_t a0[4], a1[4];
                    {
                        int r = R0 + alane;
                        uint32_t ad = ab + r * 128 + (((ks * 2 + asel) ^ (r & 7)) * 16);
                        LDMATRIX_X4(a0[0], a0[1], a0[2], a0[3], ad);
                        r = R0 + 16 + alane;
                        ad = ab + r * 128 + (((ks * 2 + asel) ^ (r & 7)) * 16);
                        LDMATRIX_X4(a1[0], a1[1], a1[2], a1[3], ad);
                    }
#pragma unroll
                    for (int gg = 0; gg < 2; ++gg) {
                        const int nr = C0 + g2 * 32 + gg * 16 + nlane;
                        const uint32_t bd = bb + nr * 128 + (((ks * 2 + bsel) ^ (nr & 7)) * 16);
                        uint32_t b0, b1, b2, b3;
                        LDMATRIX_X4(b0, b1, b2, b3, bd);
                        MMA_E4M3(p[gg*8+0], p[gg*8+1], p[gg*8+2], p[gg*8+3],
                                 a0[0], a0[1], a0[2], a0[3], b0, b1);
                        MMA_E4M3(p[gg*8+4], p[gg*8+5], p[gg*8+6], p[gg*8+7],
                                 a0[0], a0[1], a0[2], a0[3], b2, b3);
                        MMA_E4M3(p[16+gg*8+0], p[16+gg*8+1], p[16+gg*8+2], p[16+gg*8+3],
                                 a1[0], a1[1], a1[2], a1[3], b0, b1);
                        MMA_E4M3(p[16+gg*8+4], p[16+gg*8+5], p[16+gg*8+6], p[16+gg*8+7],
                                 a1[0], a1[1], a1[2], a1[3], b2, b3);
                    }
                }
                // fold per-block scales into fp32 accumulator
#pragma unroll
                for (int mh = 0; mh < 2; ++mh) {
                    const float fA = SC[R0 + mh * 16 + lr] * wv;
                    const float fB = SC[R0 + mh * 16 + 8 + lr] * wv;
#pragma unroll
                    for (int gg = 0; gg < 2; ++gg) {
#pragma unroll
                        for (int pr = 0; pr < 2; ++pr) {
                            const int pi = mh * 16 + gg * 8 + pr * 4;
                            const int ai = g2 * 32 + pi;
                            acc[ai+0] = fmaf(p[pi+0], fA, acc[ai+0]);
                            acc[ai+1] = fmaf(p[pi+1], fA, acc[ai+1]);
                            acc[ai+2] = fmaf(p[pi+2], fB, acc[ai+2]);
                            acc[ai+3] = fmaf(p[pi+3], fB, acc[ai+3]);
                        }
                    }
                }
            }
        }
        __syncthreads();
        if (kc + 2 < KB) {
            issue_b(sb, tid, kc + 2, st);
            asm volatile("cp.async.commit_group;" ::: "memory");
        }
    }

    // ================= epilogue =================
#pragma unroll
    for (int g2 = 0; g2 < 2; ++g2) {
#pragma unroll
        for (int mh = 0; mh < 2; ++mh) {
            const int row = R0 + mh * 16 + lr;
            float* o0 = out + (m0cta + row) * NDIM;
#pragma unroll
            for (int gg = 0; gg < 2; ++gg) {
#pragma unroll
                for (int pr = 0; pr < 2; ++pr) {
                    const int base = g2 * 32 + mh * 16 + gg * 8 + pr * 4;
                    const int col = C0 + g2 * 32 + gg * 16 + pr * 8 + (lane & 3) * 2;
                    *(float2*)(o0 + col) = make_float2(acc[base], acc[base+1]);
                    *(float2*)(o0 + 8 * NDIM + col) = make_float2(acc[base+2], acc[base+3]);
                }
            }
        }
    }
}

// ============================================================================
extern "C" void kernel_launch(void* const* d_in, const int* in_sizes, int n_in,
                              void* d_out, int out_size) {
    const float* x = (const float*)d_in[0];
    const void* w = d_in[1];
    const float* ws = (const float*)d_in[2];
    float* out = (float*)d_out;

    const int M = in_sizes[0] / KDIM;       // 16384
    const int grid = M / MT;                // 256

    cudaFuncSetAttribute(fused_fp8_gemm, cudaFuncAttributeMaxDynamicSharedMemorySize, SMEM_TOTAL);

    conv_kernel<<<(NDIM * KDIM / 4 + 255) / 256, 256>>>(w);
    fused_fp8_gemm<<<grid, NTH, SMEM_TOTAL>>>(x, ws, out);
}

// round 7
// speedup vs baseline: 1.1924x; 1.0503x over previous
#include <cuda_runtime.h>
#include <cstdint>

// ============================================================================
// LinearDeepSeekV3: y = act_quant(x) @ dequant(weight)^T
// M=16384, N=256, K=7168, fp8 e4m3 weight with [128x128] block scales.
// Baseline-ISA (plain sm_103): legacy mma.sync.m16n8k32.e4m3, fp32 accum.
//
// R6: de-fused quantization. R5 profiling showed the GEMM was LDS-bandwidth
// bound, half of it staging f32 activations for in-kernel quant. Now:
//   quant_kernel: x f32 -> g_x8 (fp8) + g_scT scales [kb][M] (one DRAM pass)
//   gemm: A fp8 tiles (8KB) + B fp8 tiles, dual-buffered, A-frag preload,
//         per-k-half scale folding, 2 barriers/chunk.
// ============================================================================

#define KDIM 7168
#define NDIM 256
#define KC 128
#define KB 56
#define MT 64
#define NTH 256
#define MMAX 16384

// ---- gemm shared memory layout (bytes) ----
#define OFF_BS 0            // [2][256][128] u8 = 65536 (swizzled)
#define OFF_AS 65536        // [2][64][128] u8 = 16384 (swizzled)
#define OFF_SC 81920        // [2][64] f32 = 512
#define OFF_WS 82432        // [112] f32 = 448
#define SMEM_TOTAL 82880

__device__ __align__(16) uint8_t g_w8[(size_t)NDIM * KDIM];
__device__ __align__(16) uint8_t g_x8[(size_t)MMAX * KDIM];
__device__ __align__(16) float g_scT[(size_t)KB * MMAX];

__device__ __forceinline__ uint32_t smem_u32(const void* p) {
    uint32_t a;
    asm("{ .reg .u64 t; cvta.to.shared.u64 t, %1; cvt.u32.u64 %0, t; }" : "=r"(a) : "l"(p));
    return a;
}

#define CP_ASYNC16(dst, src) \
    asm volatile("cp.async.cg.shared.global [%0], [%1], 16;" :: "r"(dst), "l"(src) : "memory")

#define LDMATRIX_X4(r0, r1, r2, r3, addr) \
    asm volatile("ldmatrix.sync.aligned.m8n8.x4.shared.b16 {%0,%1,%2,%3}, [%4];" \
        : "=r"(r0), "=r"(r1), "=r"(r2), "=r"(r3) : "r"(addr))

#define MMA_E4M3(d0, d1, d2, d3, a0, a1, a2, a3, b0, b1) \
    asm volatile("mma.sync.aligned.m16n8k32.row.col.f32.e4m3.e4m3.f32 " \
        "{%0,%1,%2,%3}, {%4,%5,%6,%7}, {%8,%9}, {%0,%1,%2,%3};" \
        : "+f"(d0), "+f"(d1), "+f"(d2), "+f"(d3) \
        : "r"(a0), "r"(a1), "r"(a2), "r"(a3), "r"(b0), "r"(b1))

// ============================================================================
// Weight canonicalization (harness upcasts fp8 inputs to f32; detect + cvt).
// ============================================================================
__global__ void conv_kernel(const void* w) {
    __shared__ int cnt;
    const int tid = threadIdx.x;
    if (tid == 0) cnt = 0;
    __syncthreads();
    const float* wf = (const float*)w;
    int ok = 0;
#pragma unroll
    for (int i = 0; i < 16; ++i) {
        float v = wf[tid + i * 256];
        if (isfinite(v) && fabsf(v) <= 1.0f) ok++;
    }
#pragma unroll
    for (int o = 16; o; o >>= 1) ok += __shfl_xor_sync(0xffffffffu, ok, o);
    if ((tid & 31) == 0) atomicAdd(&cnt, ok);
    __syncthreads();
    const bool is_f32 = (cnt >= 4000);

    const int i4 = blockIdx.x * 256 + tid;
    constexpr int TOT4 = NDIM * KDIM / 4;
    if (i4 >= TOT4) return;
    uint32_t outw;
    if (is_f32) {
        const float4 v = ((const float4*)w)[i4];
        unsigned short lo, hi;
        asm("cvt.rn.satfinite.e4m3x2.f32 %0, %1, %2;" : "=h"(lo) : "f"(v.y), "f"(v.x));
        asm("cvt.rn.satfinite.e4m3x2.f32 %0, %1, %2;" : "=h"(hi) : "f"(v.w), "f"(v.z));
        outw = (uint32_t)lo | ((uint32_t)hi << 16);
    } else {
        outw = ((const uint32_t*)w)[i4];
    }
    ((uint32_t*)g_w8)[i4] = outw;
}

// ============================================================================
// Activation quantization: one CTA per row; warp w handles k-blocks w, w+8, ...
// Exact reference numerics (amax, RN divide, e4m3 RN-satfinite).
// ============================================================================
__global__ void __launch_bounds__(256, 4)
quant_kernel(const float* __restrict__ x, int M) {
    const int m = blockIdx.x;
    const int w = threadIdx.x >> 5;
    const int lane = threadIdx.x & 31;
    const float4* xr = (const float4*)(x + (size_t)m * KDIM);
    uint32_t* xq = (uint32_t*)(g_x8 + (size_t)m * KDIM);

    float4 v[7];
#pragma unroll
    for (int i = 0; i < 7; ++i) v[i] = xr[(w + i * 8) * 32 + lane];

    float am[7];
#pragma unroll
    for (int i = 0; i < 7; ++i)
        am[i] = fmaxf(fmaxf(fabsf(v[i].x), fabsf(v[i].y)),
                      fmaxf(fabsf(v[i].z), fabsf(v[i].w)));
#pragma unroll
    for (int o = 16; o; o >>= 1) {
#pragma unroll
        for (int i = 0; i < 7; ++i)
            am[i] = fmaxf(am[i], __shfl_xor_sync(0xffffffffu, am[i], o));
    }
#pragma unroll
    for (int i = 0; i < 7; ++i) {
        const int kb = w + i * 8;
        const float amax = fmaxf(am[i], 1e-8f);
        const float s = __fdiv_rn(amax, 448.0f);
        const float ri = __fdiv_rn(448.0f, amax);
        unsigned short lo, hi;
        asm("cvt.rn.satfinite.e4m3x2.f32 %0, %1, %2;"
            : "=h"(lo) : "f"(v[i].y * ri), "f"(v[i].x * ri));
        asm("cvt.rn.satfinite.e4m3x2.f32 %0, %1, %2;"
            : "=h"(hi) : "f"(v[i].w * ri), "f"(v[i].z * ri));
        xq[kb * 32 + lane] = (uint32_t)lo | ((uint32_t)hi << 16);
        if (lane == 0) g_scT[(size_t)kb * M + m] = s;
    }
}

// ============================================================================
// fp8 mma GEMM (A = pre-quantized activations, B = canonical fp8 weights)
// ============================================================================
__device__ __forceinline__ void issue_chunk(uint32_t sb, int tid, size_t m0cta,
                                            int kc, int st, int M) {
    // A tile: 64 rows x 128 fp8 (swizzled)
    {
        const int u = tid & 7;
        const int r0 = tid >> 3;        // 0..31
#pragma unroll
        for (int i = 0; i < 2; ++i) {
            const int row = r0 + i * 32;
            const uint32_t dst = sb + OFF_AS + st * 8192 + row * 128 + ((u ^ (row & 7)) * 16);
            const uint8_t* g = g_x8 + (m0cta + row) * KDIM + (size_t)kc * KC + u * 16;
            CP_ASYNC16(dst, g);
        }
    }
    // B tile: 256 rows x 128 fp8 (swizzled)
    {
        const int u = tid & 7;
        const int n0 = tid >> 3;        // 0..31
#pragma unroll
        for (int i = 0; i < 8; ++i) {
            const int n = n0 + i * 32;
            const uint32_t dst = sb + OFF_BS + st * 32768 + n * 128 + ((u ^ (n & 7)) * 16);
            const uint8_t* g = g_w8 + (size_t)n * KDIM + (size_t)kc * KC + u * 16;
            CP_ASYNC16(dst, g);
        }
    }
    // act scales: 64 contiguous f32 from transposed table
    if (tid < 16) {
        const uint32_t dst = sb + OFF_SC + st * 256 + tid * 16;
        const float* g = g_scT + (size_t)kc * M + m0cta + tid * 4;
        CP_ASYNC16(dst, g);
    }
    asm volatile("cp.async.commit_group;" ::: "memory");
}

__global__ void __launch_bounds__(NTH, 2)
fused_fp8_gemm(const float* __restrict__ ws, float* __restrict__ out, int M) {
    extern __shared__ char smem[];
    const uint32_t sb = smem_u32(smem);
    const int tid = threadIdx.x;
    const int lane = tid & 31;
    const int wid = tid >> 5;
    const size_t m0cta = (size_t)blockIdx.x * MT;

    if (tid < 112) ((float*)(smem + OFF_WS))[tid] = ws[tid];

    // warp grid 2m x 4n, warp tile m32 x n64
    const int R0 = (wid >> 2) * 32;
    const int C0 = (wid & 3) * 64;
    const int nb = (wid & 3) >> 1;
    const int alane = lane & 15, asel = lane >> 4;
    const int nlane = (lane & 7) | ((lane >> 4) << 3);
    const int bsel = (lane >> 3) & 1;
    const int lr = lane >> 2;

    float acc[64];
#pragma unroll
    for (int i = 0; i < 64; ++i) acc[i] = 0.f;

    issue_chunk(sb, tid, m0cta, 0, 0, M);
    issue_chunk(sb, tid, m0cta, 1, 1, M);

    const float* SC = (const float*)(smem + OFF_SC);
    const float* WS = (const float*)(smem + OFF_WS);

#pragma unroll 1
    for (int kc = 0; kc < KB; ++kc) {
        const int st = kc & 1;
        if (kc == KB - 1) { asm volatile("cp.async.wait_group 0;" ::: "memory"); }
        else              { asm volatile("cp.async.wait_group 1;" ::: "memory"); }
        __syncthreads();

        const uint32_t ab = sb + OFF_AS + st * 8192;
        const uint32_t bb = sb + OFF_BS + st * 32768;
        const float wv = WS[nb * 56 + kc];
        float f[4];
#pragma unroll
        for (int mh = 0; mh < 2; ++mh) {
            f[mh * 2 + 0] = SC[st * 64 + R0 + mh * 16 + lr] * wv;
            f[mh * 2 + 1] = SC[st * 64 + R0 + mh * 16 + 8 + lr] * wv;
        }

#pragma unroll
        for (int kh = 0; kh < 2; ++kh) {
            uint32_t a[2][2][4];
#pragma unroll
            for (int ks2 = 0; ks2 < 2; ++ks2) {
#pragma unroll
                for (int mh = 0; mh < 2; ++mh) {
                    const int r = R0 + mh * 16 + alane;
                    const int ks = kh * 2 + ks2;
                    const uint32_t ad = ab + r * 128 + (((ks * 2 + asel) ^ (r & 7)) * 16);
                    LDMATRIX_X4(a[ks2][mh][0], a[ks2][mh][1], a[ks2][mh][2], a[ks2][mh][3], ad);
                }
            }
#pragma unroll
            for (int ng = 0; ng < 4; ++ng) {
                float p[16];
#pragma unroll
                for (int i = 0; i < 16; ++i) p[i] = 0.f;
#pragma unroll
                for (int ks2 = 0; ks2 < 2; ++ks2) {
                    const int nr = C0 + ng * 16 + nlane;
                    const int ks = kh * 2 + ks2;
                    const uint32_t bd = bb + nr * 128 + (((ks * 2 + bsel) ^ (nr & 7)) * 16);
                    uint32_t b0, b1, b2, b3;
                    LDMATRIX_X4(b0, b1, b2, b3, bd);
#pragma unroll
                    for (int mh = 0; mh < 2; ++mh) {
                        MMA_E4M3(p[mh*8+0], p[mh*8+1], p[mh*8+2], p[mh*8+3],
                                 a[ks2][mh][0], a[ks2][mh][1], a[ks2][mh][2], a[ks2][mh][3],
                                 b0, b1);
                        MMA_E4M3(p[mh*8+4], p[mh*8+5], p[mh*8+6], p[mh*8+7],
                                 a[ks2][mh][0], a[ks2][mh][1], a[ks2][mh][2], a[ks2][mh][3],
                                 b2, b3);
                    }
                }
#pragma unroll
                for (int mh = 0; mh < 2; ++mh) {
#pragma unroll
                    for (int pr = 0; pr < 2; ++pr) {
                        const int pi = mh * 8 + pr * 4;
                        const int ai = ng * 16 + pi;
                        acc[ai+0] = fmaf(p[pi+0], f[mh*2+0], acc[ai+0]);
                        acc[ai+1] = fmaf(p[pi+1], f[mh*2+0], acc[ai+1]);
                        acc[ai+2] = fmaf(p[pi+2], f[mh*2+1], acc[ai+2]);
                        acc[ai+3] = fmaf(p[pi+3], f[mh*2+1], acc[ai+3]);
                    }
                }
            }
        }
        __syncthreads();
        if (kc + 2 < KB) issue_chunk(sb, tid, m0cta, kc + 2, st, M);
    }

    // ================= epilogue =================
#pragma unroll
    for (int mh = 0; mh < 2; ++mh) {
        const int row = R0 + mh * 16 + lr;
        float* o0 = out + (m0cta + row) * NDIM;
#pragma unroll
        for (int ng = 0; ng < 4; ++ng) {
#pragma unroll
            for (int pr = 0; pr < 2; ++pr) {
                const int base = ng * 16 + mh * 8 + pr * 4;
                const int col = C0 + ng * 16 + pr * 8 + (lane & 3) * 2;
                *(float2*)(o0 + col) = make_float2(acc[base], acc[base+1]);
                *(float2*)(o0 + 8 * NDIM + col) = make_float2(acc[base+2], acc[base+3]);
            }
        }
    }
}

// ============================================================================
extern "C" void kernel_launch(void* const* d_in, const int* in_sizes, int n_in,
                              void* d_out, int out_size) {
    const float* x = (const float*)d_in[0];
    const void* w = d_in[1];
    const float* ws = (const float*)d_in[2];
    float* out = (float*)d_out;

    const int M = in_sizes[0] / KDIM;       // 16384
    const int grid = M / MT;                // 256

    cudaFuncSetAttribute(fused_fp8_gemm, cudaFuncAttributeMaxDynamicSharedMemorySize, SMEM_TOTAL);

    conv_kernel<<<(NDIM * KDIM / 4 + 255) / 256, 256>>>(w);
    quant_kernel<<<M, 256>>>(x, M);
    fused_fp8_gemm<<<grid, NTH, SMEM_TOTAL>>>(ws, out, M);
}